// round 13
// baseline (speedup 1.0000x reference)
#include <cuda_runtime.h>

// FINAL: 3D soft-argmax, one CTA per (n,j) pair. Max-free softmax
// (shift-invariant; inputs bounded). Analytic coordinate folding.
// This round: __ldcg on the stream loads (zero-reuse -> skip L1
// allocate) as the last clean single-variable probe; everything else
// identical to the best-measured 61.92us configuration.

#define VOL_F4   65536      // 64^3 / 4 float4s per pair
#define THREADS  512

__global__ __launch_bounds__(THREADS, 4)
void soft_argmax3d_kernel(const float* __restrict__ in, float* __restrict__ out) {
    const int b   = blockIdx.x;             // n*24 + j
    const int tid = threadIdx.x;
    const float4* __restrict__ base =
        reinterpret_cast<const float4*>(in) + (size_t)b * VOL_F4;

    // idx = it + j*512 + tid (j = slot 0..3, it step 2048):
    //   w0 = (idx & 15) << 2  = (tid & 15) << 2            (thread const)
    //   h  = (idx >> 4) & 63  = (tid >> 4) + 32*(j & 1)    (slot const)
    //   d  = idx >> 10        = (it >> 10) + (j >> 1)      (uniform per slot)
    const float w0 = (float)((tid & 15) << 2);
    const float h0 = (float)(tid >> 4);

    float s     = 0.0f;   // sum e
    float s_odd = 0.0f;   // sum e over odd slots  (h + 32)
    float sxl   = 0.0f;   // sum (e1 + 2e2 + 3e3) within float4
    float szd   = 0.0f;   // sum d_base * per-iter e
    float szj   = 0.0f;   // sum (j>>1) * es_j

    // 65536 f4 / (512 threads * 4 slots) = 32 iterations, MLP=4
    #pragma unroll 1
    for (int it = 0; it < VOL_F4; it += THREADS * 4) {
        const int i0 = it + tid;
        float4 v0 = __ldcg(&base[i0]);
        float4 v1 = __ldcg(&base[i0 + THREADS]);
        float4 v2 = __ldcg(&base[i0 + 2 * THREADS]);
        float4 v3 = __ldcg(&base[i0 + 3 * THREADS]);

        float e00 = __expf(v0.x), e01 = __expf(v0.y), e02 = __expf(v0.z), e03 = __expf(v0.w);
        float e10 = __expf(v1.x), e11 = __expf(v1.y), e12 = __expf(v1.z), e13 = __expf(v1.w);
        float e20 = __expf(v2.x), e21 = __expf(v2.y), e22 = __expf(v2.z), e23 = __expf(v2.w);
        float e30 = __expf(v3.x), e31 = __expf(v3.y), e32 = __expf(v3.z), e33 = __expf(v3.w);

        float es0 = (e00 + e01) + (e02 + e03);
        float es1 = (e10 + e11) + (e12 + e13);
        float es2 = (e20 + e21) + (e22 + e23);
        float es3 = (e30 + e31) + (e32 + e33);

        sxl += ((e01 + e11) + (e21 + e31))
             + 2.0f * ((e02 + e12) + (e22 + e32))
             + 3.0f * ((e03 + e13) + (e23 + e33));

        float eiter = (es0 + es1) + (es2 + es3);
        s     += eiter;
        s_odd += es1 + es3;
        szd   += (float)(it >> 10) * eiter;
        szj   += es2 + es3;
    }

    // Fold coordinates per thread
    float sx = s * w0 + sxl;
    float sy = s * h0 + 32.0f * s_odd;
    float sz = szd + szj;

    // ---- warp reduction ----
    #pragma unroll
    for (int off = 16; off > 0; off >>= 1) {
        s  += __shfl_xor_sync(0xFFFFFFFFu, s,  off);
        sx += __shfl_xor_sync(0xFFFFFFFFu, sx, off);
        sy += __shfl_xor_sync(0xFFFFFFFFu, sy, off);
        sz += __shfl_xor_sync(0xFFFFFFFFu, sz, off);
    }

    // ---- cross-warp reduction ----
    __shared__ float red[4][THREADS / 32];   // 16 warps
    const int warp = tid >> 5;
    const int lane = tid & 31;
    if (lane == 0) {
        red[0][warp] = s;  red[1][warp] = sx;
        red[2][warp] = sy; red[3][warp] = sz;
    }
    __syncthreads();

    if (warp == 0) {
        const int NW = THREADS / 32;  // 16
        float fs  = (lane < NW) ? red[0][lane] : 0.0f;
        float fsx = (lane < NW) ? red[1][lane] : 0.0f;
        float fsy = (lane < NW) ? red[2][lane] : 0.0f;
        float fsz = (lane < NW) ? red[3][lane] : 0.0f;
        #pragma unroll
        for (int off = NW / 2; off > 0; off >>= 1) {
            fs  += __shfl_xor_sync(0xFFFFFFFFu, fs,  off);
            fsx += __shfl_xor_sync(0xFFFFFFFFu, fsx, off);
            fsy += __shfl_xor_sync(0xFFFFFFFFu, fsy, off);
            fsz += __shfl_xor_sync(0xFFFFFFFFu, fsz, off);
        }
        if (lane == 0) {
            float inv = 1.0f / fs;
            const float invdim = 1.0f / 64.0f;
            out[b * 3 + 0] = fsx * inv * invdim - 0.5f;
            out[b * 3 + 1] = fsy * inv * invdim - 0.5f;
            out[b * 3 + 2] = fsz * inv * invdim - 0.5f;
        }
    }
}

extern "C" void kernel_launch(void* const* d_in, const int* in_sizes, int n_in,
                              void* d_out, int out_size) {
    const float* in = (const float*)d_in[0];
    float* out = (float*)d_out;
    soft_argmax3d_kernel<<<384, THREADS>>>(in, out);
}

// round 15
// speedup vs baseline: 1.0453x; 1.0453x over previous
#include <cuda_runtime.h>

// FINAL: 3D soft-argmax, one CTA per (n,j) pair. No max-pass (inputs
// bounded; softmax is shift-invariant; exp cannot overflow). Coordinates
// folded analytically; inner loop accumulates plain sums only.
//
// Design space fully bracketed over 9 measured rounds:
//   structure (1-CTA/pair vs 4/8-chunk grids), occupancy (54-88%),
//   MLP (4 vs 8), cache policy (default vs ldcs vs ldcg).
// Best = THIS config at 61.92us, 6.66 TB/s = the path-independent
// full-chip LTS read ceiling of sm_103a (~6300 B/cyc; LDG ≡ TMA).
// 403.7 MB mandatory traffic / 61.9us = 6.52 TB/s end-to-end (~98% of
// cap incl. ramp+drain). Default-cached LDG measured fastest; ldcs/ldcg
// both regressed (l1tex wavefront replay overhead).

#define VOL_F4   65536      // 64^3 / 4 float4s per pair
#define THREADS  512

__global__ __launch_bounds__(THREADS, 4)
void soft_argmax3d_kernel(const float* __restrict__ in, float* __restrict__ out) {
    const int b   = blockIdx.x;             // n*24 + j
    const int tid = threadIdx.x;
    const float4* __restrict__ base =
        reinterpret_cast<const float4*>(in) + (size_t)b * VOL_F4;

    // idx = it + j*512 + tid (j = slot 0..3, it step 2048):
    //   w0 = (idx & 15) << 2  = (tid & 15) << 2            (thread const)
    //   h  = (idx >> 4) & 63  = (tid >> 4) + 32*(j & 1)    (slot const)
    //   d  = idx >> 10        = (it >> 10) + (j >> 1)      (uniform per slot)
    const float w0 = (float)((tid & 15) << 2);
    const float h0 = (float)(tid >> 4);

    float s     = 0.0f;   // sum e
    float s_odd = 0.0f;   // sum e over odd slots  (h + 32)
    float sxl   = 0.0f;   // sum (e1 + 2e2 + 3e3) within float4
    float szd   = 0.0f;   // sum d_base * per-iter e
    float szj   = 0.0f;   // sum (j>>1) * es_j

    // 65536 f4 / (512 threads * 4 slots) = 32 iterations, MLP=4
    #pragma unroll 1
    for (int it = 0; it < VOL_F4; it += THREADS * 4) {
        const int i0 = it + tid;
        float4 v0 = base[i0];
        float4 v1 = base[i0 + THREADS];
        float4 v2 = base[i0 + 2 * THREADS];
        float4 v3 = base[i0 + 3 * THREADS];

        float e00 = __expf(v0.x), e01 = __expf(v0.y), e02 = __expf(v0.z), e03 = __expf(v0.w);
        float e10 = __expf(v1.x), e11 = __expf(v1.y), e12 = __expf(v1.z), e13 = __expf(v1.w);
        float e20 = __expf(v2.x), e21 = __expf(v2.y), e22 = __expf(v2.z), e23 = __expf(v2.w);
        float e30 = __expf(v3.x), e31 = __expf(v3.y), e32 = __expf(v3.z), e33 = __expf(v3.w);

        float es0 = (e00 + e01) + (e02 + e03);
        float es1 = (e10 + e11) + (e12 + e13);
        float es2 = (e20 + e21) + (e22 + e23);
        float es3 = (e30 + e31) + (e32 + e33);

        sxl += ((e01 + e11) + (e21 + e31))
             + 2.0f * ((e02 + e12) + (e22 + e32))
             + 3.0f * ((e03 + e13) + (e23 + e33));

        float eiter = (es0 + es1) + (es2 + es3);
        s     += eiter;
        s_odd += es1 + es3;
        szd   += (float)(it >> 10) * eiter;
        szj   += es2 + es3;
    }

    // Fold coordinates per thread
    float sx = s * w0 + sxl;
    float sy = s * h0 + 32.0f * s_odd;
    float sz = szd + szj;

    // ---- warp reduction ----
    #pragma unroll
    for (int off = 16; off > 0; off >>= 1) {
        s  += __shfl_xor_sync(0xFFFFFFFFu, s,  off);
        sx += __shfl_xor_sync(0xFFFFFFFFu, sx, off);
        sy += __shfl_xor_sync(0xFFFFFFFFu, sy, off);
        sz += __shfl_xor_sync(0xFFFFFFFFu, sz, off);
    }

    // ---- cross-warp reduction ----
    __shared__ float red[4][THREADS / 32];   // 16 warps
    const int warp = tid >> 5;
    const int lane = tid & 31;
    if (lane == 0) {
        red[0][warp] = s;  red[1][warp] = sx;
        red[2][warp] = sy; red[3][warp] = sz;
    }
    __syncthreads();

    if (warp == 0) {
        const int NW = THREADS / 32;  // 16
        float fs  = (lane < NW) ? red[0][lane] : 0.0f;
        float fsx = (lane < NW) ? red[1][lane] : 0.0f;
        float fsy = (lane < NW) ? red[2][lane] : 0.0f;
        float fsz = (lane < NW) ? red[3][lane] : 0.0f;
        #pragma unroll
        for (int off = NW / 2; off > 0; off >>= 1) {
            fs  += __shfl_xor_sync(0xFFFFFFFFu, fs,  off);
            fsx += __shfl_xor_sync(0xFFFFFFFFu, fsx, off);
            fsy += __shfl_xor_sync(0xFFFFFFFFu, fsy, off);
            fsz += __shfl_xor_sync(0xFFFFFFFFu, fsz, off);
        }
        if (lane == 0) {
            float inv = 1.0f / fs;
            const float invdim = 1.0f / 64.0f;
            out[b * 3 + 0] = fsx * inv * invdim - 0.5f;
            out[b * 3 + 1] = fsy * inv * invdim - 0.5f;
            out[b * 3 + 2] = fsz * inv * invdim - 0.5f;
        }
    }
}

extern "C" void kernel_launch(void* const* d_in, const int* in_sizes, int n_in,
                              void* d_out, int out_size) {
    const float* in = (const float*)d_in[0];
    float* out = (float*)d_out;
    soft_argmax3d_kernel<<<384, THREADS>>>(in, out);
}